// round 15
// baseline (speedup 1.0000x reference)
#include <cuda_runtime.h>
#include <cuda_bf16.h>

#define IMG_W 1024
#define IMG_H 1024
#define NC_TOTAL 48
#define ROWS 8
#define NLOAD 10
#define CHAIN 8            // tiles per CTA chain = 64 rows

// v13: v7 tile body + double-buffered chain. Each tile burst-prefetches only
// the 8 NEW rows of the next tile (overlap rows are register-renamed), cutting
// vertical read amplification 1.25x -> 1.03x. Static buffer alternation only.
template<bool PRE>
__device__ __forceinline__ void tile_db(
    const float* __restrict__ base, float* __restrict__ outnc,
    const float (&w)[9], float4 (&cur)[NLOAD], float4 (&nxt)[NLOAD],
    int y0, int lane, int x0)
{
    float num[ROWS][4], sq[ROWS][4];
    float* op = outnc + (size_t)y0 * IMG_W;

    // prologue halo for input row 0 (global row y0-1)
    float h0c = __shfl_up_sync(0xffffffffu, cur[0].w, 1);
    float h5c = __shfl_down_sync(0xffffffffu, cur[0].x, 1);
    {
        const int rr = y0 - 1;
        if (lane == 0)  h0c = (x0 > 0 && rr >= 0)          ? __ldg(base + (size_t)rr * IMG_W - 1) : 0.f;
        if (lane == 31) h5c = (x0 + 4 < IMG_W && rr >= 0)  ? __ldg(base + (size_t)rr * IMG_W + 4) : 0.f;
    }

#pragma unroll
    for (int r = 0; r < NLOAD; r++) {
        // burst-prefetch the next tile's 8 NEW rows (y1+1 .. y1+8) once cur[0..1] die
        if (PRE && r == 2) {
            const int y1 = y0 + ROWS;
            // rows y1+1 .. y1+7 always in-image (y1 <= 1016 -> y1+7 <= 1023)
#pragma unroll
            for (int i = 2; i < 9; i++)
                nxt[i] = *reinterpret_cast<const float4*>(base + (size_t)(y1 - 1 + i) * IMG_W);
            {
                const int rr = y1 + 8;
                const int rc = min(IMG_H - 1, rr);
                nxt[9] = *reinterpret_cast<const float4*>(base + (size_t)rc * IMG_W);
                if (rr != rc) nxt[9] = make_float4(0.f, 0.f, 0.f, 0.f);
            }
        }

        // next row's halo pipelined ahead of this row's compute
        float h0n = 0.f, h5n = 0.f;
        if (r + 1 < NLOAD) {
            h0n = __shfl_up_sync(0xffffffffu, cur[r + 1].w, 1);
            h5n = __shfl_down_sync(0xffffffffu, cur[r + 1].x, 1);
            const int rr = y0 + r;                 // global row of cur[r+1]
            if (lane == 0)  h0n = (x0 > 0 && rr < IMG_H)         ? __ldg(base + (size_t)rr * IMG_W - 1) : 0.f;
            if (lane == 31) h5n = (x0 + 4 < IMG_W && rr < IMG_H) ? __ldg(base + (size_t)rr * IMG_W + 4) : 0.f;
        }

        const float a[6] = { h0c, cur[r].x, cur[r].y, cur[r].z, cur[r].w, h5c };

        float p[6];
#pragma unroll
        for (int i = 0; i < 6; i++) p[i] = a[i] * a[i];
        const float u = p[1] + p[2];
        const float t = p[3] + p[4];
        const float s[4] = { p[0] + u, u + p[3], p[2] + t, t + p[5] };

#pragma unroll
        for (int o = 0; o < ROWS; o++) {
            const int k = r - o;
            if (k == 0) {
#pragma unroll
                for (int j = 0; j < 4; j++) {
                    num[o][j] = fmaf(w[0], a[j], fmaf(w[1], a[j + 1], w[2] * a[j + 2]));
                    sq[o][j] = s[j];
                }
            } else if (k == 1 || k == 2) {
                const float w0 = w[k * 3 + 0], w1 = w[k * 3 + 1], w2 = w[k * 3 + 2];
#pragma unroll
                for (int j = 0; j < 4; j++) {
                    num[o][j] = fmaf(w0, a[j], fmaf(w1, a[j + 1], fmaf(w2, a[j + 2], num[o][j])));
                    sq[o][j] += s[j];
                }
            }
        }

        // output row (r-2) complete after consuming input row r
        if (r >= 2) {
            const int o = r - 2;
            float4 ov;
            ov.x = num[o][0] * rsqrtf(sq[o][0]);
            ov.y = num[o][1] * rsqrtf(sq[o][1]);
            ov.z = num[o][2] * rsqrtf(sq[o][2]);
            ov.w = num[o][3] * rsqrtf(sq[o][3]);
            __stcs(reinterpret_cast<float4*>(op + (size_t)o * IMG_W), ov);
        }

        h0c = h0n; h5c = h5n;
    }

    // overlap rows for next tile: pure register renames (no reload)
    if (PRE) { nxt[0] = cur[8]; nxt[1] = cur[9]; }
}

__global__ void __launch_bounds__(256, 2) normconv3x3_v13(
    const float* __restrict__ x,
    const float* __restrict__ wt,
    float* __restrict__ out)
{
    const int lane = threadIdx.x & 31;
    const int x0 = (int)threadIdx.x << 2;          // 0..1020
    const int b = blockIdx.x;
    const int nc = b >> 4;                         // 0..47
    const int ycs = (b & 15) << 6;                 // chain start row (64-row chains)
    const int c = nc % 3;

    const float* base = x + ((size_t)nc << 20) + x0;
    float* outnc = out + ((size_t)nc << 20) + x0;

    float4 A[NLOAD], B[NLOAD];

    // chain-start burst: rows ycs-1 .. ycs+8 (top clamp only when ycs==0)
    if (ycs != 0) {
#pragma unroll
        for (int i = 0; i < NLOAD; i++)
            A[i] = *reinterpret_cast<const float4*>(base + (size_t)(ycs - 1 + i) * IMG_W);
    } else {
#pragma unroll
        for (int i = 0; i < NLOAD; i++) {
            const int rr = ycs - 1 + i;
            const int rc = max(0, rr);
            A[i] = *reinterpret_cast<const float4*>(base + (size_t)rc * IMG_W);
            if (rr != rc) A[i] = make_float4(0.f, 0.f, 0.f, 0.f);
        }
    }

    // weights after the burst is in flight
    float w[9];
    float ws2 = 0.f;
#pragma unroll
    for (int k = 0; k < 9; k++) { w[k] = __ldg(&wt[c * 9 + k]); ws2 += w[k] * w[k]; }
    const float winv = rsqrtf(ws2);
#pragma unroll
    for (int k = 0; k < 9; k++) w[k] *= winv;

    // 8 tiles, buffers alternating statically: even->A, odd->B
#pragma unroll 1
    for (int tp = 0; tp < 3; tp++) {
        const int y0 = ycs + tp * 16;
        tile_db<true>(base, outnc, w, A, B, y0, lane, x0);
        tile_db<true>(base, outnc, w, B, A, y0 + 8, lane, x0);
    }
    tile_db<true >(base, outnc, w, A, B, ycs + 48, lane, x0);
    tile_db<false>(base, outnc, w, B, A, ycs + 56, lane, x0);
}

extern "C" void kernel_launch(void* const* d_in, const int* in_sizes, int n_in,
                              void* d_out, int out_size) {
    const float* x  = (const float*)d_in[0];
    const float* wt = (const float*)d_in[1];
    float* out = (float*)d_out;

    dim3 grid(NC_TOTAL * (IMG_H / (CHAIN * ROWS)));   // 48 * 16 = 768 CTAs
    normconv3x3_v13<<<grid, 256>>>(x, wt, out);
}

// round 16
// speedup vs baseline: 1.0601x; 1.0601x over previous
#include <cuda_runtime.h>
#include <cuda_bf16.h>

#define IMG_W 1024
#define IMG_H 1024
#define NC_TOTAL 48
#define ROWS 8
#define NLOAD (ROWS + 2)
#define NTILES (NC_TOTAL * (IMG_H / ROWS))   // 6144
#define GRID_CTAS 456                        // 3 CTAs/SM x 152 SMs (GB300)

// v14 = v12 (v7 tile body, persistent grid-stride) + zero-cost L2 prefetch:
// while computing tile t, each thread issues prefetch.global.L2 for its 16B
// slice of all 10 rows of this CTA's NEXT tile (t + GRID_CTAS). No registers,
// no scoreboard, no smem -- DRAM reads stream continuously; demand bursts hit L2.
__device__ __forceinline__ void tile8(
    const float* __restrict__ x, const float* __restrict__ wt,
    float* __restrict__ out, int tile, int ptile, int lane, int x0)
{
    const int y0 = (tile & 127) << 3;              // 128 8-row tiles
    const int nc = tile >> 7;                      // 0..47
    const int c = nc % 3;

    const float* base = x + ((size_t)nc << 20) + x0;

    // ---- Phase 1: 10 branch-free batched row loads (MLP=10) ----
    float4 v[NLOAD];
    if (y0 != 0 && y0 != IMG_H - ROWS) {
#pragma unroll
        for (int r = 0; r < NLOAD; r++)
            v[r] = *reinterpret_cast<const float4*>(base + (size_t)(y0 - 1 + r) * IMG_W);
    } else {
#pragma unroll
        for (int r = 0; r < NLOAD; r++) {
            const int rr = y0 - 1 + r;
            const int rc = min(IMG_H - 1, max(0, rr));
            v[r] = *reinterpret_cast<const float4*>(base + (size_t)rc * IMG_W);
            if (rr != rc) v[r] = make_float4(0.f, 0.f, 0.f, 0.f);
        }
    }

    // ---- L2 prefetch of the NEXT tile (no regs, no scoreboard) ----
    {
        const int py0 = (ptile & 127) << 3;
        const int pnc = ptile >> 7;
        const float* pbase = x + ((size_t)pnc << 20) + x0;
#pragma unroll
        for (int i = 0; i < NLOAD; i++) {
            const int rr = py0 - 1 + i;
            const int rc = min(IMG_H - 1, max(0, rr));
            asm volatile("prefetch.global.L2 [%0];"
                         :: "l"(pbase + (size_t)rc * IMG_W) : "memory");
        }
    }

    // Weights (const-cache hits)
    float w[9];
    float ws2 = 0.f;
#pragma unroll
    for (int k = 0; k < 9; k++) { w[k] = __ldg(&wt[c * 9 + k]); ws2 += w[k] * w[k]; }
    const float winv = rsqrtf(ws2);
#pragma unroll
    for (int k = 0; k < 9; k++) w[k] *= winv;

    float num[ROWS][4], sq[ROWS][4];
    float* op = out + ((size_t)nc << 20) + (size_t)y0 * IMG_W + x0;

    // Prologue halo for input row 0 (global row y0-1)
    float h0c = __shfl_up_sync(0xffffffffu, v[0].w, 1);
    float h5c = __shfl_down_sync(0xffffffffu, v[0].x, 1);
    {
        const int rr = y0 - 1;
        if (lane == 0)  h0c = (x0 > 0 && rr >= 0)          ? __ldg(base + (size_t)rr * IMG_W - 1) : 0.f;
        if (lane == 31) h5c = (x0 + 4 < IMG_W && rr >= 0)  ? __ldg(base + (size_t)rr * IMG_W + 4) : 0.f;
    }

#pragma unroll
    for (int r = 0; r < NLOAD; r++) {
        // next row's halo pipelined ahead of this row's compute
        float h0n = 0.f, h5n = 0.f;
        if (r + 1 < NLOAD) {
            h0n = __shfl_up_sync(0xffffffffu, v[r + 1].w, 1);
            h5n = __shfl_down_sync(0xffffffffu, v[r + 1].x, 1);
            const int rr = y0 + r;                 // global row of v[r+1]
            if (lane == 0)  h0n = (x0 > 0 && rr < IMG_H)         ? __ldg(base + (size_t)rr * IMG_W - 1) : 0.f;
            if (lane == 31) h5n = (x0 + 4 < IMG_W && rr < IMG_H) ? __ldg(base + (size_t)rr * IMG_W + 4) : 0.f;
        }

        const float a[6] = { h0c, v[r].x, v[r].y, v[r].z, v[r].w, h5c };

        float p[6];
#pragma unroll
        for (int i = 0; i < 6; i++) p[i] = a[i] * a[i];
        const float u = p[1] + p[2];
        const float t = p[3] + p[4];
        const float s[4] = { p[0] + u, u + p[3], p[2] + t, t + p[5] };

#pragma unroll
        for (int o = 0; o < ROWS; o++) {
            const int k = r - o;                    // weight row for this (input,output) pair
            if (k == 0) {
#pragma unroll
                for (int j = 0; j < 4; j++) {
                    num[o][j] = fmaf(w[0], a[j], fmaf(w[1], a[j + 1], w[2] * a[j + 2]));
                    sq[o][j] = s[j];
                }
            } else if (k == 1 || k == 2) {
                const float w0 = w[k * 3 + 0], w1 = w[k * 3 + 1], w2 = w[k * 3 + 2];
#pragma unroll
                for (int j = 0; j < 4; j++) {
                    num[o][j] = fmaf(w0, a[j], fmaf(w1, a[j + 1], fmaf(w2, a[j + 2], num[o][j])));
                    sq[o][j] += s[j];
                }
            }
        }

        // output row (r-2) complete after consuming input row r
        if (r >= 2) {
            const int o = r - 2;
            float4 ov;
            ov.x = num[o][0] * rsqrtf(sq[o][0]);
            ov.y = num[o][1] * rsqrtf(sq[o][1]);
            ov.z = num[o][2] * rsqrtf(sq[o][2]);
            ov.w = num[o][3] * rsqrtf(sq[o][3]);
            __stcs(reinterpret_cast<float4*>(op + (size_t)o * IMG_W), ov);
        }

        h0c = h0n; h5c = h5n;
    }
}

__global__ void __launch_bounds__(256, 3) normconv3x3_v14(
    const float* __restrict__ x,
    const float* __restrict__ wt,
    float* __restrict__ out)
{
    const int lane = threadIdx.x & 31;
    const int x0 = (int)threadIdx.x << 2;          // 0..1020

    for (int tile = blockIdx.x; tile < NTILES; tile += GRID_CTAS) {
        int ptile = tile + GRID_CTAS;
        if (ptile >= NTILES) ptile = tile;         // last round: self (harmless, L2-hot)
        tile8(x, wt, out, tile, ptile, lane, x0);
    }
}

extern "C" void kernel_launch(void* const* d_in, const int* in_sizes, int n_in,
                              void* d_out, int out_size) {
    const float* x  = (const float*)d_in[0];
    const float* wt = (const float*)d_in[1];
    float* out = (float*)d_out;

    normconv3x3_v14<<<GRID_CTAS, 256>>>(x, wt, out);
}

// round 17
// speedup vs baseline: 1.2776x; 1.2052x over previous
#include <cuda_runtime.h>
#include <cuda_bf16.h>

#define IMG_W 1024
#define IMG_H 1024
#define NC_TOTAL 48
#define ROWS 8
#define NLOAD (ROWS + 2)

// v15 = v7 (proven optimum: 10 front-batched row loads, 8-row tile, pipelined
// shuffle halo, early store) with the denominator restructured: per-row window
// sums s[] kept in a 3-deep rotating window (free renaming in unrolled code);
// q = sm2+sm1+s computed once at store time. 120 -> 64 adds per tile, sq[][] gone.
__global__ void __launch_bounds__(256, 3) normconv3x3_v15(
    const float* __restrict__ x,
    const float* __restrict__ wt,
    float* __restrict__ out)
{
    const int lane = threadIdx.x & 31;
    const int x0 = (int)threadIdx.x << 2;          // 0..1020
    const int b = blockIdx.x;
    const int y0 = (b & 127) << 3;                 // 128 8-row tiles
    const int nc = b >> 7;                         // 0..47
    const int c = nc % 3;

    const float* base = x + ((size_t)nc << 20) + x0;

    // ---- Phase 1: 10 branch-free batched row loads (MLP=10) ----
    float4 v[NLOAD];
    if (y0 != 0 && y0 != IMG_H - ROWS) {
#pragma unroll
        for (int r = 0; r < NLOAD; r++)
            v[r] = *reinterpret_cast<const float4*>(base + (size_t)(y0 - 1 + r) * IMG_W);
    } else {
#pragma unroll
        for (int r = 0; r < NLOAD; r++) {
            const int rr = y0 - 1 + r;
            const int rc = min(IMG_H - 1, max(0, rr));
            v[r] = *reinterpret_cast<const float4*>(base + (size_t)rc * IMG_W);
            if (rr != rc) v[r] = make_float4(0.f, 0.f, 0.f, 0.f);
        }
    }

    // Weights after the bulk loads are in flight (const-cache hits)
    float w[9];
    float ws2 = 0.f;
#pragma unroll
    for (int k = 0; k < 9; k++) { w[k] = __ldg(&wt[c * 9 + k]); ws2 += w[k] * w[k]; }
    const float winv = rsqrtf(ws2);
#pragma unroll
    for (int k = 0; k < 9; k++) w[k] *= winv;

    float num[ROWS][4];
    float sm1[4], sm2[4];                          // s of rows r-1, r-2 (renamed, not shifted)
    float* op = out + ((size_t)nc << 20) + (size_t)y0 * IMG_W + x0;

    // Prologue halo for input row 0 (global row y0-1)
    float h0c = __shfl_up_sync(0xffffffffu, v[0].w, 1);
    float h5c = __shfl_down_sync(0xffffffffu, v[0].x, 1);
    {
        const int rr = y0 - 1;
        if (lane == 0)  h0c = (x0 > 0 && rr >= 0)          ? __ldg(base + (size_t)rr * IMG_W - 1) : 0.f;
        if (lane == 31) h5c = (x0 + 4 < IMG_W && rr >= 0)  ? __ldg(base + (size_t)rr * IMG_W + 4) : 0.f;
    }

#pragma unroll
    for (int r = 0; r < NLOAD; r++) {
        // next row's halo pipelined ahead of this row's compute
        float h0n = 0.f, h5n = 0.f;
        if (r + 1 < NLOAD) {
            h0n = __shfl_up_sync(0xffffffffu, v[r + 1].w, 1);
            h5n = __shfl_down_sync(0xffffffffu, v[r + 1].x, 1);
            const int rr = y0 + r;                 // global row of v[r+1]
            if (lane == 0)  h0n = (x0 > 0 && rr < IMG_H)         ? __ldg(base + (size_t)rr * IMG_W - 1) : 0.f;
            if (lane == 31) h5n = (x0 + 4 < IMG_W && rr < IMG_H) ? __ldg(base + (size_t)rr * IMG_W + 4) : 0.f;
        }

        const float a[6] = { h0c, v[r].x, v[r].y, v[r].z, v[r].w, h5c };

        // current row's squared 3-window sums
        float p[6];
#pragma unroll
        for (int i = 0; i < 6; i++) p[i] = a[i] * a[i];
        const float u = p[1] + p[2];
        const float t = p[3] + p[4];
        const float s[4] = { p[0] + u, u + p[3], p[2] + t, t + p[5] };

        // numerator accumulation (3 output rows touched per input row)
#pragma unroll
        for (int o = 0; o < ROWS; o++) {
            const int k = r - o;                    // weight row for this (input,output) pair
            if (k == 0) {
#pragma unroll
                for (int j = 0; j < 4; j++)
                    num[o][j] = fmaf(w[0], a[j], fmaf(w[1], a[j + 1], w[2] * a[j + 2]));
            } else if (k == 1 || k == 2) {
                const float w0 = w[k * 3 + 0], w1 = w[k * 3 + 1], w2 = w[k * 3 + 2];
#pragma unroll
                for (int j = 0; j < 4; j++)
                    num[o][j] = fmaf(w0, a[j], fmaf(w1, a[j + 1], fmaf(w2, a[j + 2], num[o][j])));
            }
        }

        // output row (r-2): denominator = sm2 + sm1 + s, computed only here
        if (r >= 2) {
            const int o = r - 2;
            float4 ov;
            ov.x = num[o][0] * rsqrtf(sm2[0] + sm1[0] + s[0]);
            ov.y = num[o][1] * rsqrtf(sm2[1] + sm1[1] + s[1]);
            ov.z = num[o][2] * rsqrtf(sm2[2] + sm1[2] + s[2]);
            ov.w = num[o][3] * rsqrtf(sm2[3] + sm1[3] + s[3]);
            *reinterpret_cast<float4*>(op + (size_t)o * IMG_W) = ov;
        }

        // rotate the s window (register renames in fully unrolled code)
#pragma unroll
        for (int j = 0; j < 4; j++) { sm2[j] = sm1[j]; sm1[j] = s[j]; }

        h0c = h0n; h5c = h5n;
    }
}

extern "C" void kernel_launch(void* const* d_in, const int* in_sizes, int n_in,
                              void* d_out, int out_size) {
    const float* x  = (const float*)d_in[0];
    const float* wt = (const float*)d_in[1];
    float* out = (float*)d_out;

    dim3 grid(NC_TOTAL * (IMG_H / ROWS));   // 6144 blocks, 256 threads = full row width
    normconv3x3_v15<<<grid, 256>>>(x, wt, out);
}